// round 8
// baseline (speedup 1.0000x reference)
#include <cuda_runtime.h>
#include <cuda_fp16.h>
#include <cstdint>

#define NMAX 50000
#define EMAX 800000
#define FIN  128
#define FH   128
#define FOUT 64

// ---------------- scratch (device globals; allocation-free) ----------------
__device__ int    g_cnt[NMAX];
__device__ int    g_scan[NMAX];
__device__ int    g_part[256];
__device__ int    g_partx[256];
__device__ int    g_off[NMAX + 1];
__device__ int    g_cur[NMAX];
__device__ int    g_srcs[EMAX];
__device__ float  g_w[EMAX];
__device__ float  g_isd[NMAX];
__device__ float  g_idg[NMAX];
__device__ __half g_h1[(size_t)NMAX * FH];
__device__ float  g_agg1[(size_t)NMAX * FH];
__device__ __half g_h2[(size_t)NMAX * FOUT];

// ---------------------------------------------------------------------------
// CSR build — R2's proven parallel pipeline (unchanged)
// ---------------------------------------------------------------------------
__global__ void k_zero(int n) {
    int i = blockIdx.x * blockDim.x + threadIdx.x;
    if (i < n) g_cnt[i] = 0;
}

__global__ void k_count(const int* __restrict__ dst, int e) {
    int i = blockIdx.x * blockDim.x + threadIdx.x;
    if (i < e) atomicAdd(&g_cnt[dst[i]], 1);
}

__global__ void k_scan1(int n) {
    __shared__ int sh[256];
    int tid = threadIdx.x;
    int i = blockIdx.x * 256 + tid;
    int v = (i < n) ? g_cnt[i] : 0;
    sh[tid] = v;
    __syncthreads();
#pragma unroll
    for (int d = 1; d < 256; d <<= 1) {
        int t = (tid >= d) ? sh[tid - d] : 0;
        __syncthreads();
        sh[tid] += t;
        __syncthreads();
    }
    if (i < n) g_scan[i] = sh[tid];
    if (tid == 255) g_part[blockIdx.x] = sh[255];
}

__global__ void k_scan2(int nb) {
    __shared__ int sh[256];
    int tid = threadIdx.x;
    int v = (tid < nb) ? g_part[tid] : 0;
    sh[tid] = v;
    __syncthreads();
#pragma unroll
    for (int d = 1; d < 256; d <<= 1) {
        int t = (tid >= d) ? sh[tid - d] : 0;
        __syncthreads();
        sh[tid] += t;
        __syncthreads();
    }
    if (tid < nb) g_partx[tid] = sh[tid] - v;
}

__global__ void k_scan3(int n, int e) {
    int i = blockIdx.x * blockDim.x + threadIdx.x;
    if (i < n) {
        int c = g_cnt[i];
        int excl = g_scan[i] - c + g_partx[blockIdx.x];
        g_off[i] = excl;
        g_cur[i] = excl;
        float deg = (float)c + 1.0f;
        g_isd[i] = rsqrtf(deg);
        g_idg[i] = 1.0f / deg;
    }
    if (i == 0) g_off[n] = e;
}

__global__ void k_fill(const int* __restrict__ src, const int* __restrict__ dst, int e) {
    int i = blockIdx.x * blockDim.x + threadIdx.x;
    if (i < e) {
        int s = src[i];
        int d = dst[i];
        int pos = atomicAdd(&g_cur[d], 1);
        g_srcs[pos] = s;
        g_w[pos] = g_isd[s] * g_isd[d];
    }
}

// ---------------------------------------------------------------------------
// SGEMM (R2's proven tile: BM=128, BN=64, BK=16, 256 thr, 8x4) — only the
// epilogue changed: store fp16 via native __half2 stores.
// ---------------------------------------------------------------------------
template <int F, bool RELU_A>
__global__ void __launch_bounds__(256)
k_gemm(const float* __restrict__ A, const float* __restrict__ W,
       __half* __restrict__ Hout, int N) {
    constexpr int K = 128, BM = 128, BN = 64, BK = 16;
    __shared__ float As[BK][BM + 4];
    __shared__ float Ws[BK][BN];

    const int tid = threadIdx.x;
    const int rowBase = blockIdx.y * BM;
    const int colBase = blockIdx.x * BN;
    const int ty = tid >> 4;
    const int tx = tid & 15;
    const int wk = tid >> 4;
    const int wn = (tid & 15) * 4;

    float acc[8][4];
#pragma unroll
    for (int i = 0; i < 8; i++)
#pragma unroll
        for (int j = 0; j < 4; j++) acc[i][j] = 0.0f;

    for (int k0 = 0; k0 < K; k0 += BK) {
#pragma unroll
        for (int l = 0; l < 2; l++) {
            int idx = tid + l * 256;
            int row = idx >> 2;
            int kq = (idx & 3) * 4;
            int r = rowBase + row;
            float4 av = make_float4(0.f, 0.f, 0.f, 0.f);
            if (r < N)
                av = *reinterpret_cast<const float4*>(A + (size_t)r * K + k0 + kq);
            if (RELU_A) {
                av.x = fmaxf(av.x, 0.f); av.y = fmaxf(av.y, 0.f);
                av.z = fmaxf(av.z, 0.f); av.w = fmaxf(av.w, 0.f);
            }
            As[kq + 0][row] = av.x;
            As[kq + 1][row] = av.y;
            As[kq + 2][row] = av.z;
            As[kq + 3][row] = av.w;
        }
        *reinterpret_cast<float4*>(&Ws[wk][wn]) =
            *reinterpret_cast<const float4*>(W + (size_t)(k0 + wk) * F + colBase + wn);
        __syncthreads();

#pragma unroll
        for (int k = 0; k < BK; k++) {
            float4 a0 = *reinterpret_cast<const float4*>(&As[k][ty * 8]);
            float4 a1 = *reinterpret_cast<const float4*>(&As[k][ty * 8 + 4]);
            float4 bv = *reinterpret_cast<const float4*>(&Ws[k][tx * 4]);
            float a[8] = {a0.x, a0.y, a0.z, a0.w, a1.x, a1.y, a1.z, a1.w};
            float b[4] = {bv.x, bv.y, bv.z, bv.w};
#pragma unroll
            for (int i = 0; i < 8; i++)
#pragma unroll
                for (int j = 0; j < 4; j++) acc[i][j] = fmaf(a[i], b[j], acc[i][j]);
        }
        __syncthreads();
    }

    // Epilogue: fp16 stores (native __half2, global-pointer cast only)
    const int col = colBase + tx * 4;
    __half2* Hp = reinterpret_cast<__half2*>(Hout);
#pragma unroll
    for (int i = 0; i < 8; i++) {
        int row = rowBase + ty * 8 + i;
        if (row < N) {
            size_t base = ((size_t)row * F + col) >> 1;   // index in __half2 units
            Hp[base + 0] = __floats2half2_rn(acc[i][0], acc[i][1]);
            Hp[base + 1] = __floats2half2_rn(acc[i][2], acc[i][3]);
        }
    }
}

// ---------------------------------------------------------------------------
// CSR gather from fp16 H (R2's structure, 2-way unroll): warp per node.
//   Out[d] = sum_{e: dst=d} H[src_e]*w_e + H[d]*idg[d] + bias   (fp32 accum)
// All H access via native __half2 global loads.
// ---------------------------------------------------------------------------
template <int F>
__global__ void __launch_bounds__(256)
k_gather(const __half* __restrict__ H, const float* __restrict__ bias,
         float* __restrict__ Out, int N) {
    int gw = (blockIdx.x * blockDim.x + threadIdx.x) >> 5;
    int lane = threadIdx.x & 31;
    if (gw >= N) return;
    const int beg = g_off[gw];
    const int end = g_off[gw + 1];
    const __half2* __restrict__ Hp = reinterpret_cast<const __half2*>(H);

    if (F == 128) {
        // 64 half2 per row; lane handles half2 slots lane*2, lane*2+1
        const size_t rbase = (size_t)gw * 64 + lane * 2;
        float idg = g_idg[gw];
        float2 h0 = __half22float2(Hp[rbase]);
        float2 h1 = __half22float2(Hp[rbase + 1]);
        float4 bv = *reinterpret_cast<const float4*>(bias + lane * 4);
        float4 acc = make_float4(fmaf(h0.x, idg, bv.x), fmaf(h0.y, idg, bv.y),
                                 fmaf(h1.x, idg, bv.z), fmaf(h1.y, idg, bv.w));
        int j = beg;
        for (; j + 1 < end; j += 2) {
            size_t r0 = (size_t)g_srcs[j] * 64 + lane * 2;
            size_t r1 = (size_t)g_srcs[j + 1] * 64 + lane * 2;
            float w0 = g_w[j], w1 = g_w[j + 1];
            float2 a0 = __half22float2(Hp[r0]);
            float2 b0 = __half22float2(Hp[r0 + 1]);
            float2 a1 = __half22float2(Hp[r1]);
            float2 b1 = __half22float2(Hp[r1 + 1]);
            acc.x = fmaf(a0.x, w0, acc.x); acc.y = fmaf(a0.y, w0, acc.y);
            acc.z = fmaf(b0.x, w0, acc.z); acc.w = fmaf(b0.y, w0, acc.w);
            acc.x = fmaf(a1.x, w1, acc.x); acc.y = fmaf(a1.y, w1, acc.y);
            acc.z = fmaf(b1.x, w1, acc.z); acc.w = fmaf(b1.y, w1, acc.w);
        }
        if (j < end) {
            size_t r = (size_t)g_srcs[j] * 64 + lane * 2;
            float w = g_w[j];
            float2 a = __half22float2(Hp[r]);
            float2 b = __half22float2(Hp[r + 1]);
            acc.x = fmaf(a.x, w, acc.x); acc.y = fmaf(a.y, w, acc.y);
            acc.z = fmaf(b.x, w, acc.z); acc.w = fmaf(b.y, w, acc.w);
        }
        *reinterpret_cast<float4*>(Out + (size_t)gw * 128 + lane * 4) = acc;
    } else {
        // F=64: 32 half2 per row; lane handles slot `lane`
        const size_t rbase = (size_t)gw * 32 + lane;
        float idg = g_idg[gw];
        float2 hv = __half22float2(Hp[rbase]);
        float2 bv = *reinterpret_cast<const float2*>(bias + lane * 2);
        float2 acc = make_float2(fmaf(hv.x, idg, bv.x), fmaf(hv.y, idg, bv.y));
        int j = beg;
        for (; j + 1 < end; j += 2) {
            size_t r0 = (size_t)g_srcs[j] * 32 + lane;
            size_t r1 = (size_t)g_srcs[j + 1] * 32 + lane;
            float w0 = g_w[j], w1 = g_w[j + 1];
            float2 v0 = __half22float2(Hp[r0]);
            float2 v1 = __half22float2(Hp[r1]);
            acc.x = fmaf(v0.x, w0, acc.x); acc.y = fmaf(v0.y, w0, acc.y);
            acc.x = fmaf(v1.x, w1, acc.x); acc.y = fmaf(v1.y, w1, acc.y);
        }
        if (j < end) {
            size_t r = (size_t)g_srcs[j] * 32 + lane;
            float w = g_w[j];
            float2 v = __half22float2(Hp[r]);
            acc.x = fmaf(v.x, w, acc.x); acc.y = fmaf(v.y, w, acc.y);
        }
        *reinterpret_cast<float2*>(Out + (size_t)gw * 64 + lane * 2) = acc;
    }
}

// ---------------------------------------------------------------------------
// Launch: R2's exact serial structure.
// ---------------------------------------------------------------------------
extern "C" void kernel_launch(void* const* d_in, const int* in_sizes, int n_in,
                              void* d_out, int out_size) {
    const float* x  = (const float*)d_in[0];
    const int* eidx = (const int*)d_in[1];
    const float* W1 = (const float*)d_in[2];
    const float* b1 = (const float*)d_in[3];
    const float* W2 = (const float*)d_in[4];
    const float* b2 = (const float*)d_in[5];
    float* out = (float*)d_out;

    const int N = in_sizes[0] / FIN;   // 50000
    const int E = in_sizes[1] / 2;     // 800000
    const int* src = eidx;
    const int* dst = eidx + E;

    __half *h1, *h2;
    float *agg1;
    cudaGetSymbolAddress((void**)&h1, g_h1);
    cudaGetSymbolAddress((void**)&agg1, g_agg1);
    cudaGetSymbolAddress((void**)&h2, g_h2);

    const int nScanBlocks = (N + 255) / 256;

    // CSR build (R2 proven)
    k_zero<<<nScanBlocks, 256>>>(N);
    k_count<<<(E + 255) / 256, 256>>>(dst, E);
    k_scan1<<<nScanBlocks, 256>>>(N);
    k_scan2<<<1, 256>>>(nScanBlocks);
    k_scan3<<<nScanBlocks, 256>>>(N, E);
    k_fill<<<(E + 255) / 256, 256>>>(src, dst, E);

    const int rowBlocks = (N + 127) / 128;
    const int gatherBlocks = (N * 32 + 255) / 256;

    // Layer 1
    {
        dim3 grid(FH / 64, rowBlocks);
        k_gemm<FH, false><<<grid, 256>>>(x, W1, h1, N);
    }
    k_gather<FH><<<gatherBlocks, 256>>>(h1, b1, agg1, N);

    // Layer 2
    {
        dim3 grid(FOUT / 64, rowBlocks);
        k_gemm<FOUT, true><<<grid, 256>>>(agg1, W2, h2, N);
    }
    k_gather<FOUT><<<gatherBlocks, 256>>>(h2, b2, out, N);
}

// round 9
// speedup vs baseline: 1.0897x; 1.0897x over previous
#include <cuda_runtime.h>
#include <cuda_fp16.h>
#include <cstdint>

#define NMAX 50000
#define EMAX 800000
#define FIN  128
#define FH   128
#define FOUT 64

// ---------------- scratch (device globals; allocation-free) ----------------
__device__ int    g_cnt[NMAX];
__device__ int    g_scan[NMAX];
__device__ int    g_part[256];
__device__ int    g_off[NMAX + 1];
__device__ int    g_cur[NMAX];
__device__ int    g_srcs[EMAX];
__device__ float  g_w[EMAX];
__device__ float  g_isd[NMAX];
__device__ float  g_idg[NMAX];
__device__ __half g_h1[(size_t)NMAX * FH];
__device__ float  g_agg1[(size_t)NMAX * FH];
__device__ __half g_h2[(size_t)NMAX * FOUT];

// ---------------------------------------------------------------------------
// CSR build — parallel kernels only (no cross-block forward-progress deps,
// safe to co-schedule with GEMM-1; the R3 spin-chain lesson).
// ---------------------------------------------------------------------------
__global__ void k_count(const int* __restrict__ dst, int e) {
    int i = blockIdx.x * blockDim.x + threadIdx.x;
    if (i < e) atomicAdd(&g_cnt[dst[i]], 1);
}

__global__ void k_scan1(int n) {
    __shared__ int sh[256];
    int tid = threadIdx.x;
    int i = blockIdx.x * 256 + tid;
    int v = (i < n) ? g_cnt[i] : 0;
    sh[tid] = v;
    __syncthreads();
#pragma unroll
    for (int d = 1; d < 256; d <<= 1) {
        int t = (tid >= d) ? sh[tid - d] : 0;
        __syncthreads();
        sh[tid] += t;
        __syncthreads();
    }
    if (i < n) g_scan[i] = sh[tid];
    if (tid == 255) g_part[blockIdx.x] = sh[255];
}

// Fused scan2+scan3: each block recomputes its own block-prefix by reducing
// g_part[0..b-1] (nb <= 256 -> one 256-thread reduction), then finalizes
// offsets/cursors/degree terms. Removes the idle single-block scan2 kernel.
__global__ void k_scan23(int n, int e) {
    __shared__ int sh[256];
    const int b = blockIdx.x;
    const int tid = threadIdx.x;

    sh[tid] = (tid < b) ? g_part[tid] : 0;
    __syncthreads();
#pragma unroll
    for (int d = 128; d > 0; d >>= 1) {
        if (tid < d) sh[tid] += sh[tid + d];
        __syncthreads();
    }
    const int blockPrefix = sh[0];

    int i = b * 256 + tid;
    if (i < n) {
        int c = g_cnt[i];
        int excl = g_scan[i] - c + blockPrefix;
        g_off[i] = excl;
        g_cur[i] = excl;
        float deg = (float)c + 1.0f;
        g_isd[i] = rsqrtf(deg);
        g_idg[i] = 1.0f / deg;
    }
    if (i == 0) g_off[n] = e;
}

__global__ void k_fill(const int* __restrict__ src, const int* __restrict__ dst, int e) {
    int i = blockIdx.x * blockDim.x + threadIdx.x;
    if (i < e) {
        int s = src[i];
        int d = dst[i];
        int pos = atomicAdd(&g_cur[d], 1);
        g_srcs[pos] = s;
        g_w[pos] = g_isd[s] * g_isd[d];
    }
}

// ---------------------------------------------------------------------------
// SGEMM (proven tile: BM=128, BN=64, BK=16, 256 thr, 8x4), fp16 epilogue.
// ---------------------------------------------------------------------------
template <int F, bool RELU_A>
__global__ void __launch_bounds__(256)
k_gemm(const float* __restrict__ A, const float* __restrict__ W,
       __half* __restrict__ Hout, int N) {
    constexpr int K = 128, BM = 128, BN = 64, BK = 16;
    __shared__ float As[BK][BM + 4];
    __shared__ float Ws[BK][BN];

    const int tid = threadIdx.x;
    const int rowBase = blockIdx.y * BM;
    const int colBase = blockIdx.x * BN;
    const int ty = tid >> 4;
    const int tx = tid & 15;
    const int wk = tid >> 4;
    const int wn = (tid & 15) * 4;

    float acc[8][4];
#pragma unroll
    for (int i = 0; i < 8; i++)
#pragma unroll
        for (int j = 0; j < 4; j++) acc[i][j] = 0.0f;

    for (int k0 = 0; k0 < K; k0 += BK) {
#pragma unroll
        for (int l = 0; l < 2; l++) {
            int idx = tid + l * 256;
            int row = idx >> 2;
            int kq = (idx & 3) * 4;
            int r = rowBase + row;
            float4 av = make_float4(0.f, 0.f, 0.f, 0.f);
            if (r < N)
                av = *reinterpret_cast<const float4*>(A + (size_t)r * K + k0 + kq);
            if (RELU_A) {
                av.x = fmaxf(av.x, 0.f); av.y = fmaxf(av.y, 0.f);
                av.z = fmaxf(av.z, 0.f); av.w = fmaxf(av.w, 0.f);
            }
            As[kq + 0][row] = av.x;
            As[kq + 1][row] = av.y;
            As[kq + 2][row] = av.z;
            As[kq + 3][row] = av.w;
        }
        *reinterpret_cast<float4*>(&Ws[wk][wn]) =
            *reinterpret_cast<const float4*>(W + (size_t)(k0 + wk) * F + colBase + wn);
        __syncthreads();

#pragma unroll
        for (int k = 0; k < BK; k++) {
            float4 a0 = *reinterpret_cast<const float4*>(&As[k][ty * 8]);
            float4 a1 = *reinterpret_cast<const float4*>(&As[k][ty * 8 + 4]);
            float4 bv = *reinterpret_cast<const float4*>(&Ws[k][tx * 4]);
            float a[8] = {a0.x, a0.y, a0.z, a0.w, a1.x, a1.y, a1.z, a1.w};
            float b[4] = {bv.x, bv.y, bv.z, bv.w};
#pragma unroll
            for (int i = 0; i < 8; i++)
#pragma unroll
                for (int j = 0; j < 4; j++) acc[i][j] = fmaf(a[i], b[j], acc[i][j]);
        }
        __syncthreads();
    }

    const int col = colBase + tx * 4;
    __half2* Hp = reinterpret_cast<__half2*>(Hout);
#pragma unroll
    for (int i = 0; i < 8; i++) {
        int row = rowBase + ty * 8 + i;
        if (row < N) {
            size_t base = ((size_t)row * F + col) >> 1;
            Hp[base + 0] = __floats2half2_rn(acc[i][0], acc[i][1]);
            Hp[base + 1] = __floats2half2_rn(acc[i][2], acc[i][3]);
        }
    }
}

// ---------------------------------------------------------------------------
// CSR gather from fp16 H (proven 2-way unroll): warp per node.
// ---------------------------------------------------------------------------
template <int F>
__global__ void __launch_bounds__(256)
k_gather(const __half* __restrict__ H, const float* __restrict__ bias,
         float* __restrict__ Out, int N) {
    int gw = (blockIdx.x * blockDim.x + threadIdx.x) >> 5;
    int lane = threadIdx.x & 31;
    if (gw >= N) return;
    const int beg = g_off[gw];
    const int end = g_off[gw + 1];
    const __half2* __restrict__ Hp = reinterpret_cast<const __half2*>(H);

    if (F == 128) {
        const size_t rbase = (size_t)gw * 64 + lane * 2;
        float idg = g_idg[gw];
        float2 h0 = __half22float2(Hp[rbase]);
        float2 h1 = __half22float2(Hp[rbase + 1]);
        float4 bv = *reinterpret_cast<const float4*>(bias + lane * 4);
        float4 acc = make_float4(fmaf(h0.x, idg, bv.x), fmaf(h0.y, idg, bv.y),
                                 fmaf(h1.x, idg, bv.z), fmaf(h1.y, idg, bv.w));
        int j = beg;
        for (; j + 1 < end; j += 2) {
            size_t r0 = (size_t)g_srcs[j] * 64 + lane * 2;
            size_t r1 = (size_t)g_srcs[j + 1] * 64 + lane * 2;
            float w0 = g_w[j], w1 = g_w[j + 1];
            float2 a0 = __half22float2(Hp[r0]);
            float2 b0 = __half22float2(Hp[r0 + 1]);
            float2 a1 = __half22float2(Hp[r1]);
            float2 b1 = __half22float2(Hp[r1 + 1]);
            acc.x = fmaf(a0.x, w0, acc.x); acc.y = fmaf(a0.y, w0, acc.y);
            acc.z = fmaf(b0.x, w0, acc.z); acc.w = fmaf(b0.y, w0, acc.w);
            acc.x = fmaf(a1.x, w1, acc.x); acc.y = fmaf(a1.y, w1, acc.y);
            acc.z = fmaf(b1.x, w1, acc.z); acc.w = fmaf(b1.y, w1, acc.w);
        }
        if (j < end) {
            size_t r = (size_t)g_srcs[j] * 64 + lane * 2;
            float w = g_w[j];
            float2 a = __half22float2(Hp[r]);
            float2 b = __half22float2(Hp[r + 1]);
            acc.x = fmaf(a.x, w, acc.x); acc.y = fmaf(a.y, w, acc.y);
            acc.z = fmaf(b.x, w, acc.z); acc.w = fmaf(b.y, w, acc.w);
        }
        *reinterpret_cast<float4*>(Out + (size_t)gw * 128 + lane * 4) = acc;
    } else {
        const size_t rbase = (size_t)gw * 32 + lane;
        float idg = g_idg[gw];
        float2 hv = __half22float2(Hp[rbase]);
        float2 bv = *reinterpret_cast<const float2*>(bias + lane * 2);
        float2 acc = make_float2(fmaf(hv.x, idg, bv.x), fmaf(hv.y, idg, bv.y));
        int j = beg;
        for (; j + 1 < end; j += 2) {
            size_t r0 = (size_t)g_srcs[j] * 32 + lane;
            size_t r1 = (size_t)g_srcs[j + 1] * 32 + lane;
            float w0 = g_w[j], w1 = g_w[j + 1];
            float2 v0 = __half22float2(Hp[r0]);
            float2 v1 = __half22float2(Hp[r1]);
            acc.x = fmaf(v0.x, w0, acc.x); acc.y = fmaf(v0.y, w0, acc.y);
            acc.x = fmaf(v1.x, w1, acc.x); acc.y = fmaf(v1.y, w1, acc.y);
        }
        if (j < end) {
            size_t r = (size_t)g_srcs[j] * 32 + lane;
            float w = g_w[j];
            float2 v = __half22float2(Hp[r]);
            acc.x = fmaf(v.x, w, acc.x); acc.y = fmaf(v.y, w, acc.y);
        }
        *reinterpret_cast<float2*>(Out + (size_t)gw * 64 + lane * 2) = acc;
    }
}

// ---------------------------------------------------------------------------
// Launch: build overlapped with GEMM-1 (all build kernels parallel-safe).
// ---------------------------------------------------------------------------
extern "C" void kernel_launch(void* const* d_in, const int* in_sizes, int n_in,
                              void* d_out, int out_size) {
    const float* x  = (const float*)d_in[0];
    const int* eidx = (const int*)d_in[1];
    const float* W1 = (const float*)d_in[2];
    const float* b1 = (const float*)d_in[3];
    const float* W2 = (const float*)d_in[4];
    const float* b2 = (const float*)d_in[5];
    float* out = (float*)d_out;

    const int N = in_sizes[0] / FIN;   // 50000
    const int E = in_sizes[1] / 2;     // 800000
    const int* src = eidx;
    const int* dst = eidx + E;

    static cudaStream_t s2 = nullptr;
    static cudaEvent_t evFork = nullptr, evBuild = nullptr;
    if (!s2) {
        cudaStreamCreateWithFlags(&s2, cudaStreamNonBlocking);
        cudaEventCreateWithFlags(&evFork, cudaEventDisableTiming);
        cudaEventCreateWithFlags(&evBuild, cudaEventDisableTiming);
    }

    __half *h1, *h2;
    float *agg1;
    void *cntp;
    cudaGetSymbolAddress((void**)&h1, g_h1);
    cudaGetSymbolAddress((void**)&agg1, g_agg1);
    cudaGetSymbolAddress((void**)&h2, g_h2);
    cudaGetSymbolAddress(&cntp, g_cnt);

    const int nScanBlocks = (N + 255) / 256;
    const int rowBlocks = (N + 127) / 128;
    const int gatherBlocks = (N * 32 + 255) / 256;

    // Fork: CSR build on s2 (parallel kernels only), GEMM-1 on main stream.
    cudaEventRecord(evFork, 0);
    cudaStreamWaitEvent(s2, evFork, 0);

    cudaMemsetAsync(cntp, 0, (size_t)N * sizeof(int), s2);
    k_count<<<(E + 255) / 256, 256, 0, s2>>>(dst, E);
    k_scan1<<<nScanBlocks, 256, 0, s2>>>(N);
    k_scan23<<<nScanBlocks, 256, 0, s2>>>(N, E);
    k_fill<<<(E + 255) / 256, 256, 0, s2>>>(src, dst, E);
    cudaEventRecord(evBuild, s2);

    // GEMM-1 concurrently on main stream.
    {
        dim3 grid(FH / 64, rowBlocks);
        k_gemm<FH, false><<<grid, 256>>>(x, W1, h1, N);
    }

    // Join, then serial tail.
    cudaStreamWaitEvent(0, evBuild, 0);
    k_gather<FH><<<gatherBlocks, 256>>>(h1, b1, agg1, N);
    {
        dim3 grid(FOUT / 64, rowBlocks);
        k_gemm<FOUT, true><<<grid, 256>>>(agg1, W2, h2, N);
    }
    k_gather<FOUT><<<gatherBlocks, 256>>>(h2, b2, out, N);
}